// round 5
// baseline (speedup 1.0000x reference)
#include <cuda_runtime.h>

// LSTM: B=32768, T=28, IN=28, H=8, gates i,j,f,o; FORGET_BIAS=1.0
// R5: R4 was latency-bound (occ 10%, issue 30%, fma 26%): 1.73 warps/SMSP
// can't hide LDS lat 29. Split each element across a LANE PAIR: even lane
// owns hidden g=0..3, odd owns g=4..7; each computes its (i,f),(j,o) gate
// pairs (f32x2), activations, c/h; h halves exchanged via shfl.xor(1).
// 2x warps (2048), half per-thread work/regs -> same FMA floor, 2x hiding.

#define T_STEPS 28
#define IN_DIM 28
#define NH 8
#define NC 10
#define TPB 64

typedef unsigned long long u64;

__device__ __forceinline__ u64 pack2(float lo, float hi) {
    u64 r;
    asm("mov.b64 %0, {%1, %2};" : "=l"(r) : "f"(lo), "f"(hi));
    return r;
}
__device__ __forceinline__ void unpack2(u64 v, float& lo, float& hi) {
    asm("mov.b64 {%0, %1}, %2;" : "=f"(lo), "=f"(hi) : "l"(v));
}
__device__ __forceinline__ u64 fma2(u64 a, u64 b, u64 c) {
    u64 d;
    asm("fma.rn.f32x2 %0, %1, %2, %3;" : "=l"(d) : "l"(a), "l"(b), "l"(c));
    return d;
}
__device__ __forceinline__ float rcp_fast(float x) {
    float r;
    asm("rcp.approx.ftz.f32 %0, %1;" : "=f"(r) : "f"(x));
    return r;
}
__device__ __forceinline__ float ex2_fast(float x) {
    float r;
    asm("ex2.approx.ftz.f32 %0, %1;" : "=f"(r) : "f"(x));
    return r;
}

#define LOG2E 1.4426950408889634f

__device__ __forceinline__ float sigmoid_f(float x) {
    return rcp_fast(1.0f + ex2_fast(-x * LOG2E));
}
__device__ __forceinline__ float tanh_f(float x) {
    return 1.0f - 2.0f * rcp_fast(1.0f + ex2_fast(2.0f * LOG2E * x));
}

// Half-row FMA: this thread's 8 gate-pairs for weight row k.
// accA = (i,f) pairs for g=ho..ho+3, accB = (j,o) pairs for same g.
__device__ __forceinline__ void gate_fma_half(u64* accA, u64* accB,
                                              const u64* sWrow, int ho,
                                              float v) {
    u64 xp = pack2(v, v);
    const ulonglong2* wa = reinterpret_cast<const ulonglong2*>(sWrow + ho);
    const ulonglong2* wb = reinterpret_cast<const ulonglong2*>(sWrow + 8 + ho);
    ulonglong2 a0 = wa[0], a1 = wa[1];
    ulonglong2 b0 = wb[0], b1 = wb[1];
    accA[0] = fma2(xp, a0.x, accA[0]);
    accA[1] = fma2(xp, a0.y, accA[1]);
    accA[2] = fma2(xp, a1.x, accA[2]);
    accA[3] = fma2(xp, a1.y, accA[3]);
    accB[0] = fma2(xp, b0.x, accB[0]);
    accB[1] = fma2(xp, b0.y, accB[1]);
    accB[2] = fma2(xp, b1.x, accB[2]);
    accB[3] = fma2(xp, b1.y, accB[3]);
}

__global__ void __launch_bounds__(TPB, 5)   // reg cap 204: headroom, no spill
lstm_kernel(const float* __restrict__ x,
            const float* __restrict__ W,     // [36, 32]
            const float* __restrict__ b,     // [32]
            const float* __restrict__ ow,    // [8, 10]
            const float* __restrict__ ob,    // [10]
            float* __restrict__ out,         // [B, 10]
            int B)
{
    // sW[k*16 + g] = (W[k][g], W[k][g+16]) : g<8 -> (i_g,f_g), g=8+j -> (j_j,o_j)
    __shared__ __align__(16) u64 sW[36 * 16];
    __shared__ __align__(16) u64 sB[16];
    __shared__ float sOw[NH * NC];
    __shared__ float sOb[NC];

    const int tid = threadIdx.x;

    for (int idx = tid; idx < 36 * 16; idx += TPB) {
        int k = idx >> 4, g = idx & 15;
        sW[idx] = pack2(W[k * 32 + g], W[k * 32 + g + 16]);
    }
    if (tid < 16) {
        float hi = b[tid + 16] + (tid < 8 ? 1.0f : 0.0f);  // FORGET_BIAS in f
        sB[tid] = pack2(b[tid], hi);
    }
    for (int idx = tid; idx < NH * NC; idx += TPB) sOw[idx] = ow[idx];
    if (tid < NC) sOb[tid] = ob[tid];
    __syncthreads();

    const int gtid = blockIdx.x * TPB + tid;
    const int elem = gtid >> 1;           // two threads per batch element
    const int ho   = (tid & 1) * 4;       // hidden offset: 0 or 4
    if (elem >= B) return;

    const float4* __restrict__ xin =
        reinterpret_cast<const float4*>(x + (size_t)elem * (T_STEPS * IN_DIM));

    // bias pairs in registers (read once)
    u64 bA[4], bB[4];
#pragma unroll
    for (int g = 0; g < 4; g++) {
        bA[g] = sB[ho + g];
        bB[g] = sB[8 + ho + g];
    }

    float c[4];                 // this thread's cell states (g = ho..ho+3)
    float hk[NH];               // full hidden state (assembled via shfl)
#pragma unroll
    for (int g = 0; g < 4; g++) c[g] = 0.0f;
#pragma unroll
    for (int k = 0; k < NH; k++) hk[k] = 0.0f;

#pragma unroll 1
    for (int t = 0; t < T_STEPS; t++) {
        u64 accA[4], accB[4];
#pragma unroll
        for (int g = 0; g < 4; g++) { accA[g] = bA[g]; accB[g] = bB[g]; }

        // x contribution: 7 groups of 4 rows, rolled + 1-deep prefetch
        float4 cur = xin[t * 7];
#pragma unroll 1
        for (int i = 0; i < 7; i++) {
            float4 nxt = (i < 6) ? xin[t * 7 + i + 1] : cur;
            gate_fma_half(accA, accB, &sW[(4 * i + 0) * 16], ho, cur.x);
            gate_fma_half(accA, accB, &sW[(4 * i + 1) * 16], ho, cur.y);
            gate_fma_half(accA, accB, &sW[(4 * i + 2) * 16], ho, cur.z);
            gate_fma_half(accA, accB, &sW[(4 * i + 3) * 16], ho, cur.w);
            cur = nxt;
        }
        // h contribution: 8 rows
#pragma unroll 2
        for (int k = 0; k < NH; k++)
            gate_fma_half(accA, accB, &sW[(IN_DIM + k) * 16], ho, hk[k]);

        // activations for this thread's 4 hidden units
        float hl[4];
#pragma unroll
        for (int g = 0; g < 4; g++) {
            float ai, af, aj, ao;
            unpack2(accA[g], ai, af);
            unpack2(accB[g], aj, ao);
            float is = sigmoid_f(ai);
            float fs = sigmoid_f(af);
            float jt = tanh_f(aj);
            float os = sigmoid_f(ao);
            float cn = c[g] * fs + is * jt;
            c[g] = cn;
            hl[g] = tanh_f(cn) * os;
        }

        // exchange halves with partner lane (lane ^ 1)
#pragma unroll
        for (int g = 0; g < 4; g++) {
            float hr = __shfl_xor_sync(0xffffffffu, hl[g], 1);
            hk[ho + g] = hl[g];
            hk[(ho ^ 4) + g] = hr;
        }
    }

    // output projection: even lane writes classes 0..4, odd 5..9
    float* __restrict__ po = out + (size_t)elem * NC;
    const int c0 = (tid & 1) * 5;
#pragma unroll
    for (int cls = 0; cls < 5; cls++) {
        float a = sOb[c0 + cls];
#pragma unroll
        for (int k = 0; k < NH; k++) a += hk[k] * sOw[k * NC + c0 + cls];
        po[c0 + cls] = a;
    }
}

extern "C" void kernel_launch(void* const* d_in, const int* in_sizes, int n_in,
                              void* d_out, int out_size) {
    const float* x  = (const float*)d_in[0];
    const float* W  = (const float*)d_in[1];
    const float* b  = (const float*)d_in[2];
    const float* ow = (const float*)d_in[3];
    const float* ob = (const float*)d_in[4];
    float* out = (float*)d_out;

    const int B = in_sizes[0] / (T_STEPS * IN_DIM);
    const int threads_total = 2 * B;
    const int grid = (threads_total + TPB - 1) / TPB;
    lstm_kernel<<<grid, TPB>>>(x, W, b, ow, ob, out, B);
}